// round 1
// baseline (speedup 1.0000x reference)
#include <cuda_runtime.h>
#include <math.h>

#define NB   8
#define NC   256
#define NH   128
#define NW   128
#define NHW  (NH * NW)        // 16384
#define NHEADS 8
#define NHD  32

// Scratch (device globals: allocation-guard safe)
__device__ float g_q[NB * NC * NHW];
__device__ float g_k[NB * NC * NHW];
__device__ float g_v[NB * NC * NHW];
__device__ float g_att[NB * NC * NHW];

// ---------------------------------------------------------------------------
// Projection GEMM: Y[b][o][hw] = sum_c Wm[o][c] * X[b][c][hw] + bias[o]
// CTA tile 128(o) x 128(hw), K-chunk 16, 8x8 register tile, 256 threads.
// ---------------------------------------------------------------------------
__global__ __launch_bounds__(256) void proj_gemm(
    const float* __restrict__ X, const float* __restrict__ Wm,
    const float* __restrict__ bias, float* __restrict__ Y) {
  __shared__ float Ws[16][132];   // [k][o]  (transposed weight tile, padded)
  __shared__ float Xs[16][128];   // [k][hw]

  const int b  = blockIdx.z;
  const float* Xb = X + (size_t)b * NC * NHW;
  float*       Yb = Y + (size_t)b * NC * NHW;
  const int o0 = blockIdx.y * 128;
  const int n0 = blockIdx.x * 128;

  const int tid = threadIdx.x;
  const int tx = tid & 15;        // hw tile coord (8 cols each)
  const int ty = tid >> 4;        // o tile coord  (8 rows each)

  float acc[8][8];
#pragma unroll
  for (int i = 0; i < 8; i++)
#pragma unroll
    for (int j = 0; j < 8; j++) acc[i][j] = 0.f;

  for (int k0 = 0; k0 < NC; k0 += 16) {
    // Load W tile [128 o x 16 k] transposed into Ws[k][o]
    {
      const int o  = tid >> 1;
      const int kc = (tid & 1) * 8;
      const float* src = Wm + (size_t)(o0 + o) * NC + k0 + kc;
      float4 v0 = *(const float4*)(src);
      float4 v1 = *(const float4*)(src + 4);
      Ws[kc + 0][o] = v0.x; Ws[kc + 1][o] = v0.y;
      Ws[kc + 2][o] = v0.z; Ws[kc + 3][o] = v0.w;
      Ws[kc + 4][o] = v1.x; Ws[kc + 5][o] = v1.y;
      Ws[kc + 6][o] = v1.z; Ws[kc + 7][o] = v1.w;
    }
    // Load X tile [16 k x 128 hw]
    {
#pragma unroll
      for (int i = 0; i < 2; i++) {
        int f   = tid * 2 + i;            // 0..511 float4 slots
        int kc  = f >> 5;
        int hw4 = (f & 31) << 2;
        *(float4*)(&Xs[kc][hw4]) =
            *(const float4*)(Xb + (size_t)(k0 + kc) * NHW + n0 + hw4);
      }
    }
    __syncthreads();

#pragma unroll
    for (int kc = 0; kc < 16; kc++) {
      float a[8], bb[8];
      *(float4*)(a)     = *(const float4*)(&Ws[kc][ty * 8]);
      *(float4*)(a + 4) = *(const float4*)(&Ws[kc][ty * 8 + 4]);
      *(float4*)(bb)     = *(const float4*)(&Xs[kc][tx * 8]);
      *(float4*)(bb + 4) = *(const float4*)(&Xs[kc][tx * 8 + 4]);
#pragma unroll
      for (int i = 0; i < 8; i++)
#pragma unroll
        for (int j = 0; j < 8; j++) acc[i][j] += a[i] * bb[j];
    }
    __syncthreads();
  }

  // Epilogue: bias + store
  const int orow = o0 + ty * 8;
  const int col  = n0 + tx * 8;
#pragma unroll
  for (int i = 0; i < 8; i++) {
    float bi = bias[orow + i];
    float4 v0 = make_float4(acc[i][0] + bi, acc[i][1] + bi,
                            acc[i][2] + bi, acc[i][3] + bi);
    float4 v1 = make_float4(acc[i][4] + bi, acc[i][5] + bi,
                            acc[i][6] + bi, acc[i][7] + bi);
    float* dst = Yb + (size_t)(orow + i) * NHW + col;
    *(float4*)(dst)     = v0;
    *(float4*)(dst + 4) = v1;
  }
}

// ---------------------------------------------------------------------------
// Attention: one CTA per (b, head, d) channel slice (2048 slices).
// S = scale * Q Q·Kᵀ (contract over W), softmax over y, O = P·V.
// smem: two 128x132 buffers. Buffer0: Qᵀ[w][x] -> Pᵀ[y][x].
//       Buffer1: Kᵀ[w][y] -> V[y][w].
// ---------------------------------------------------------------------------
__global__ __launch_bounds__(256) void attn_kernel(
    const float* __restrict__ gq, const float* __restrict__ gk,
    const float* __restrict__ gv, float* __restrict__ go) {
  extern __shared__ float sm[];
  float* QT = sm;                 // [128][132]
  float* KT = sm + 128 * 132;    // [128][132]

  const size_t base = (size_t)blockIdx.x * NHW;
  const int tid = threadIdx.x;
  const int tx = tid & 15;        // y tile coord (then w in 2nd GEMM)
  const int ty = tid >> 4;        // x tile coord

  // Load Q and K transposed: QT[w][x], KT[w][y]
  for (int e = tid; e < NHW; e += 256) {
    int r = e >> 7;               // row (x or y)
    int w = e & 127;              // width coord
    QT[w * 132 + r] = gq[base + e];
    KT[w * 132 + r] = gk[base + e];
  }
  __syncthreads();

  float acc[8][8];
#pragma unroll
  for (int i = 0; i < 8; i++)
#pragma unroll
    for (int j = 0; j < 8; j++) acc[i][j] = 0.f;

  // S GEMM: acc[i][j] = sum_w Q[x0+i][w] * K[y0+j][w]
#pragma unroll 4
  for (int w = 0; w < 128; w++) {
    float a[8], bb[8];
    *(float4*)(a)      = *(const float4*)(&QT[w * 132 + ty * 8]);
    *(float4*)(a + 4)  = *(const float4*)(&QT[w * 132 + ty * 8 + 4]);
    *(float4*)(bb)     = *(const float4*)(&KT[w * 132 + tx * 8]);
    *(float4*)(bb + 4) = *(const float4*)(&KT[w * 132 + tx * 8 + 4]);
#pragma unroll
    for (int i = 0; i < 8; i++)
#pragma unroll
      for (int j = 0; j < 8; j++) acc[i][j] += a[i] * bb[j];
  }

  // Softmax over y per row x (reduce across 16 tx lanes; xor<=8 stays in group)
  const float SCALE = 0.42044820762685725f;   // 32^(-1/4)
#pragma unroll
  for (int i = 0; i < 8; i++) {
    float m = -1e30f;
#pragma unroll
    for (int j = 0; j < 8; j++) {
      float s = acc[i][j] * SCALE;
      acc[i][j] = s;
      m = fmaxf(m, s);
    }
    m = fmaxf(m, __shfl_xor_sync(0xffffffffu, m, 8));
    m = fmaxf(m, __shfl_xor_sync(0xffffffffu, m, 4));
    m = fmaxf(m, __shfl_xor_sync(0xffffffffu, m, 2));
    m = fmaxf(m, __shfl_xor_sync(0xffffffffu, m, 1));
    float sum = 0.f;
#pragma unroll
    for (int j = 0; j < 8; j++) {
      float e = __expf(acc[i][j] - m);
      acc[i][j] = e;
      sum += e;
    }
    sum += __shfl_xor_sync(0xffffffffu, sum, 8);
    sum += __shfl_xor_sync(0xffffffffu, sum, 4);
    sum += __shfl_xor_sync(0xffffffffu, sum, 2);
    sum += __shfl_xor_sync(0xffffffffu, sum, 1);
    float r = 1.0f / sum;
#pragma unroll
    for (int j = 0; j < 8; j++) acc[i][j] *= r;
  }

  __syncthreads();   // all threads done reading QT/KT

  // Store Pᵀ into QT buffer: PT[y][x]
#pragma unroll
  for (int i = 0; i < 8; i++)
#pragma unroll
    for (int j = 0; j < 8; j++)
      QT[(tx * 8 + j) * 132 + ty * 8 + i] = acc[i][j];

  // Load V into KT buffer: VS[y][w]
  for (int e = tid; e < NHW; e += 256) {
    int r = e >> 7;
    int w = e & 127;
    KT[r * 132 + w] = gv[base + e];
  }
  __syncthreads();

  // O GEMM: O[x][w] = sum_y P[x][y] * V[y][w]
#pragma unroll
  for (int i = 0; i < 8; i++)
#pragma unroll
    for (int j = 0; j < 8; j++) acc[i][j] = 0.f;

#pragma unroll 4
  for (int y = 0; y < 128; y++) {
    float a[8], bb[8];
    *(float4*)(a)      = *(const float4*)(&QT[y * 132 + ty * 8]);
    *(float4*)(a + 4)  = *(const float4*)(&QT[y * 132 + ty * 8 + 4]);
    *(float4*)(bb)     = *(const float4*)(&KT[y * 132 + tx * 8]);
    *(float4*)(bb + 4) = *(const float4*)(&KT[y * 132 + tx * 8 + 4]);
#pragma unroll
    for (int i = 0; i < 8; i++)
#pragma unroll
      for (int j = 0; j < 8; j++) acc[i][j] += a[i] * bb[j];
  }

  // Store O (layout [b][c][x][w])
#pragma unroll
  for (int i = 0; i < 8; i++) {
    float* dst = go + base + (size_t)(ty * 8 + i) * NW + tx * 8;
    *(float4*)(dst)     = make_float4(acc[i][0], acc[i][1], acc[i][2], acc[i][3]);
    *(float4*)(dst + 4) = make_float4(acc[i][4], acc[i][5], acc[i][6], acc[i][7]);
  }
}

// ---------------------------------------------------------------------------
extern "C" void kernel_launch(void* const* d_in, const int* in_sizes, int n_in,
                              void* d_out, int out_size) {
  const float* x  = (const float*)d_in[0];
  const float* wq = (const float*)d_in[1];
  const float* bq = (const float*)d_in[2];
  const float* wk = (const float*)d_in[3];
  const float* bk = (const float*)d_in[4];
  const float* wv = (const float*)d_in[5];
  const float* bv = (const float*)d_in[6];
  const float* wo = (const float*)d_in[7];
  const float* bo = (const float*)d_in[8];

  float *q, *k, *v, *att;
  cudaGetSymbolAddress((void**)&q,   g_q);
  cudaGetSymbolAddress((void**)&k,   g_k);
  cudaGetSymbolAddress((void**)&v,   g_v);
  cudaGetSymbolAddress((void**)&att, g_att);

  const int SMEM_ATTN = 2 * 128 * 132 * sizeof(float);   // 135168 B
  cudaFuncSetAttribute(attn_kernel,
                       cudaFuncAttributeMaxDynamicSharedMemorySize, SMEM_ATTN);

  dim3 grid(NHW / 128, NC / 128, NB);
  proj_gemm<<<grid, 256>>>(x, wq, bq, q);
  proj_gemm<<<grid, 256>>>(x, wk, bk, k);
  proj_gemm<<<grid, 256>>>(x, wv, bv, v);
  attn_kernel<<<NB * NC, 256, SMEM_ATTN>>>(q, k, v, att);
  proj_gemm<<<grid, 256>>>(att, wo, bo, (float*)d_out);
}

// round 3
// speedup vs baseline: 1.5726x; 1.5726x over previous
#include <cuda_runtime.h>
#include <cuda_bf16.h>
#include <cstdint>
#include <math.h>

#define NB   8
#define NC   256
#define NH   128
#define NW   128
#define NHW  (NH * NW)        // 16384

// ---------------------------------------------------------------------------
// Scratch (device globals: allocation-guard safe)
// ---------------------------------------------------------------------------
__device__ float g_q[NB * NC * NHW];
__device__ float g_k[NB * NC * NHW];
__device__ float g_v[NB * NC * NHW];
__device__ float g_att[NB * NC * NHW];
__device__ __nv_bfloat16 g_x_hi[(size_t)NB * NC * NHW];   // [b][c][n]
__device__ __nv_bfloat16 g_x_lo[(size_t)NB * NC * NHW];
__device__ __nv_bfloat16 g_w_hi[4 * NC * NC];             // wq,wk,wv,wo [o][c]
__device__ __nv_bfloat16 g_w_lo[4 * NC * NC];

// ---------------------------------------------------------------------------
// PTX helpers: ldmatrix / mma.sync (sm_80 baseline, works on sm_103) / cp.async
// ---------------------------------------------------------------------------
__device__ __forceinline__ uint32_t smem_u32(const void* p) {
  uint32_t a;
  asm("{ .reg .u64 t; cvta.to.shared.u64 t, %1; cvt.u32.u64 %0, t; }"
      : "=r"(a) : "l"(p));
  return a;
}

__device__ __forceinline__ void cp_async16(uint32_t sdst, const void* gsrc) {
  asm volatile("cp.async.cg.shared.global [%0], [%1], 16;"
               :: "r"(sdst), "l"(gsrc));
}
#define CP_COMMIT() asm volatile("cp.async.commit_group;" ::: "memory")
#define CP_WAIT0()  asm volatile("cp.async.wait_group 0;" ::: "memory")

__device__ __forceinline__ void ldsm_x4(uint32_t* r, uint32_t addr) {
  asm volatile("ldmatrix.sync.aligned.m8n8.x4.shared.b16 {%0,%1,%2,%3}, [%4];"
               : "=r"(r[0]), "=r"(r[1]), "=r"(r[2]), "=r"(r[3]) : "r"(addr));
}
__device__ __forceinline__ void ldsm_x4_t(uint32_t* r, uint32_t addr) {
  asm volatile("ldmatrix.sync.aligned.m8n8.x4.trans.shared.b16 {%0,%1,%2,%3}, [%4];"
               : "=r"(r[0]), "=r"(r[1]), "=r"(r[2]), "=r"(r[3]) : "r"(addr));
}
__device__ __forceinline__ void mma_bf16(float* d, const uint32_t* a,
                                         const uint32_t* b) {
  asm volatile(
      "mma.sync.aligned.m16n8k16.row.col.f32.bf16.bf16.f32 "
      "{%0,%1,%2,%3}, {%4,%5,%6,%7}, {%8,%9}, {%0,%1,%2,%3};"
      : "+f"(d[0]), "+f"(d[1]), "+f"(d[2]), "+f"(d[3])
      : "r"(a[0]), "r"(a[1]), "r"(a[2]), "r"(a[3]), "r"(b[0]), "r"(b[1]));
}

// ---------------------------------------------------------------------------
// Elementwise bf16 split: fp32 -> hi + lo (same layout)
// ---------------------------------------------------------------------------
__global__ __launch_bounds__(256) void split_f32(
    const float* __restrict__ X, __nv_bfloat16* __restrict__ H,
    __nv_bfloat16* __restrict__ L) {
  int i = blockIdx.x * 256 + threadIdx.x;     // float4 index
  float4 v = ((const float4*)X)[i];
  __nv_bfloat16 h0 = __float2bfloat16(v.x);
  __nv_bfloat16 h1 = __float2bfloat16(v.y);
  __nv_bfloat16 h2 = __float2bfloat16(v.z);
  __nv_bfloat16 h3 = __float2bfloat16(v.w);
  __nv_bfloat16 l0 = __float2bfloat16(v.x - __bfloat162float(h0));
  __nv_bfloat16 l1 = __float2bfloat16(v.y - __bfloat162float(h1));
  __nv_bfloat16 l2 = __float2bfloat16(v.z - __bfloat162float(h2));
  __nv_bfloat16 l3 = __float2bfloat16(v.w - __bfloat162float(h3));
  __nv_bfloat162 hp0 = {h0, h1}, hp1 = {h2, h3};
  __nv_bfloat162 lp0 = {l0, l1}, lp1 = {l2, l3};
  ((uint2*)H)[i] = make_uint2(*(uint32_t*)&hp0, *(uint32_t*)&hp1);
  ((uint2*)L)[i] = make_uint2(*(uint32_t*)&lp0, *(uint32_t*)&lp1);
}

__global__ __launch_bounds__(256) void convert_w(
    const float* __restrict__ w0, const float* __restrict__ w1,
    const float* __restrict__ w2, const float* __restrict__ w3,
    __nv_bfloat16* __restrict__ H, __nv_bfloat16* __restrict__ L) {
  const float* ws[4] = {w0, w1, w2, w3};
  int m = blockIdx.y;
  int i = blockIdx.x * 256 + threadIdx.x;
  float v = ws[m][i];
  __nv_bfloat16 h = __float2bfloat16(v);
  H[m * NC * NC + i] = h;
  L[m * NC * NC + i] = __float2bfloat16(v - __bfloat162float(h));
}

// ---------------------------------------------------------------------------
// mma.sync bf16-split GEMM: D[o][n] = sum_c W[o][c] * X[c][n] + bias[o]
// CTA tile 128(o) x 128(n), K chunks of 32, double-buffered cp.async.
// 8 warps: wm = wid&3 (o, 32 rows), wn = wid>>2 (n, 64 cols).
// smem strides padded for conflict-free ldmatrix: A 80B rows, B 272B rows.
// ---------------------------------------------------------------------------
#define A_LDA    40                    // elements (80 B)
#define B_LDB    136                   // elements (272 B)
#define OFF_AH   0
#define OFF_AL   10240                 // 128*40*2
#define OFF_BH   20480
#define OFF_BL   29184                 // 20480 + 32*136*2
#define BUF_BYTES 37888
#define SMEM_GEMM (2 * BUF_BYTES)      // 75776

__global__ __launch_bounds__(256) void gemm_mma(
    const __nv_bfloat16* __restrict__ Xh, const __nv_bfloat16* __restrict__ Xl,
    const __nv_bfloat16* __restrict__ Wh, const __nv_bfloat16* __restrict__ Wl,
    const float* __restrict__ bias, float* __restrict__ Y) {
  extern __shared__ __align__(16) char sm[];
  const uint32_t smb = smem_u32(sm);

  const int tid  = threadIdx.x;
  const int lane = tid & 31;
  const int wid  = tid >> 5;
  const int wm   = wid & 3;            // o warp tile
  const int wn   = wid >> 2;           // n warp tile
  const int b    = blockIdx.z;
  const int n0   = blockIdx.x * 128;
  const int o0   = blockIdx.y * 128;

  const __nv_bfloat16* Xbh = Xh + (size_t)b * NC * NHW + n0;
  const __nv_bfloat16* Xbl = Xl + (size_t)b * NC * NHW + n0;
  const __nv_bfloat16* Wbh = Wh + (size_t)o0 * NC;
  const __nv_bfloat16* Wbl = Wl + (size_t)o0 * NC;

  // Staging task decomposition (per chunk):
  // A: 128 rows x 4 segs of 16B; B: 32 rows x 16 segs of 16B.
  const int a_row0 = tid >> 2, a_seg = tid & 3;       // + 64 rows second pass
  const int b_row0 = tid >> 4, b_seg = tid & 15;      // + 16 rows second pass

  float acc[2][8][4];
#pragma unroll
  for (int mt = 0; mt < 2; mt++)
#pragma unroll
    for (int nt = 0; nt < 8; nt++)
#pragma unroll
      for (int e = 0; e < 4; e++) acc[mt][nt][e] = 0.f;

  // ldmatrix per-thread byte offsets (within buffer)
  const int lr = lane & 15, lc = lane >> 4;
  // A: row = wm*32 + mt*16 + lr ; col bytes = ks*32 + lc*16
  uint32_t a_base = (uint32_t)((wm * 32 + lr) * 80 + lc * 16);
  // B: row = ks*16 + lr ; col bytes = wn*128 + nt2*32 + lc*16
  uint32_t b_base = (uint32_t)(lr * 272 + wn * 128 + lc * 16);

  auto stage = [&](int it) {
    const int c0 = it * 32;
    const uint32_t sb = smb + (it & 1) * BUF_BYTES;
#pragma unroll
    for (int r = 0; r < 2; r++) {
      int row = a_row0 + r * 64;
      uint32_t so = (uint32_t)(row * 80 + a_seg * 16);
      const __nv_bfloat16* gh = Wbh + (size_t)row * NC + c0 + a_seg * 8;
      const __nv_bfloat16* gl = Wbl + (size_t)row * NC + c0 + a_seg * 8;
      cp_async16(sb + OFF_AH + so, gh);
      cp_async16(sb + OFF_AL + so, gl);
    }
#pragma unroll
    for (int r = 0; r < 2; r++) {
      int row = b_row0 + r * 16;
      uint32_t so = (uint32_t)(row * 272 + b_seg * 16);
      const __nv_bfloat16* gh = Xbh + (size_t)(c0 + row) * NHW + b_seg * 8;
      const __nv_bfloat16* gl = Xbl + (size_t)(c0 + row) * NHW + b_seg * 8;
      cp_async16(sb + OFF_BH + so, gh);
      cp_async16(sb + OFF_BL + so, gl);
    }
    CP_COMMIT();
  };

  stage(0);

  for (int it = 0; it < 8; it++) {
    CP_WAIT0();
    __syncthreads();
    if (it + 1 < 8) stage(it + 1);

    const uint32_t sb = smb + (it & 1) * BUF_BYTES;
#pragma unroll
    for (int ks = 0; ks < 2; ks++) {
      uint32_t ah[2][4], al[2][4];
#pragma unroll
      for (int mt = 0; mt < 2; mt++) {
        uint32_t ao = sb + a_base + (uint32_t)(mt * 16 * 80 + ks * 32);
        ldsm_x4(ah[mt], ao + OFF_AH);
        ldsm_x4(al[mt], ao + OFF_AL);
      }
#pragma unroll
      for (int nt2 = 0; nt2 < 4; nt2++) {
        uint32_t bh[4], bl[4];
        uint32_t bo = sb + b_base + (uint32_t)(ks * 16 * 272 + nt2 * 32);
        ldsm_x4_t(bh, bo + OFF_BH);
        ldsm_x4_t(bl, bo + OFF_BL);
#pragma unroll
        for (int mt = 0; mt < 2; mt++) {
          mma_bf16(acc[mt][nt2 * 2],     ah[mt], bh);
          mma_bf16(acc[mt][nt2 * 2 + 1], ah[mt], bh + 2);
          mma_bf16(acc[mt][nt2 * 2],     ah[mt], bl);
          mma_bf16(acc[mt][nt2 * 2 + 1], ah[mt], bl + 2);
          mma_bf16(acc[mt][nt2 * 2],     al[mt], bh);
          mma_bf16(acc[mt][nt2 * 2 + 1], al[mt], bh + 2);
        }
      }
    }
    __syncthreads();
  }

  // Epilogue: bias + store (D fragment: rows t/4 & t/4+8, cols (t%4)*2,+1)
  float* Yb = Y + (size_t)b * NC * NHW;
#pragma unroll
  for (int mt = 0; mt < 2; mt++) {
    int o = o0 + wm * 32 + mt * 16 + (lane >> 2);
    float bv0 = __ldg(bias + o);
    float bv1 = __ldg(bias + o + 8);
#pragma unroll
    for (int nt = 0; nt < 8; nt++) {
      int n = n0 + wn * 64 + nt * 8 + (lane & 3) * 2;
      float2 v0 = make_float2(acc[mt][nt][0] + bv0, acc[mt][nt][1] + bv0);
      float2 v1 = make_float2(acc[mt][nt][2] + bv1, acc[mt][nt][3] + bv1);
      *(float2*)(Yb + (size_t)o * NHW + n)       = v0;
      *(float2*)(Yb + (size_t)(o + 8) * NHW + n) = v1;
    }
  }
}

// ---------------------------------------------------------------------------
// Attention (known-good fp32 SIMT): one CTA per (b, head, d) slice.
// ---------------------------------------------------------------------------
__global__ __launch_bounds__(256) void attn_kernel(
    const float* __restrict__ gq, const float* __restrict__ gk,
    const float* __restrict__ gv, float* __restrict__ go) {
  extern __shared__ float smf[];
  float* QT = smf;                 // [128][132]
  float* KT = smf + 128 * 132;     // [128][132]

  const size_t base = (size_t)blockIdx.x * NHW;
  const int tid = threadIdx.x;
  const int tx = tid & 15;
  const int ty = tid >> 4;

  for (int e = tid; e < NHW; e += 256) {
    int r = e >> 7;
    int w = e & 127;
    QT[w * 132 + r] = gq[base + e];
    KT[w * 132 + r] = gk[base + e];
  }
  __syncthreads();

  float acc[8][8];
#pragma unroll
  for (int i = 0; i < 8; i++)
#pragma unroll
    for (int j = 0; j < 8; j++) acc[i][j] = 0.f;

#pragma unroll 4
  for (int w = 0; w < 128; w++) {
    float a[8], bb[8];
    *(float4*)(a)      = *(const float4*)(&QT[w * 132 + ty * 8]);
    *(float4*)(a + 4)  = *(const float4*)(&QT[w * 132 + ty * 8 + 4]);
    *(float4*)(bb)     = *(const float4*)(&KT[w * 132 + tx * 8]);
    *(float4*)(bb + 4) = *(const float4*)(&KT[w * 132 + tx * 8 + 4]);
#pragma unroll
    for (int i = 0; i < 8; i++)
#pragma unroll
      for (int j = 0; j < 8; j++) acc[i][j] += a[i] * bb[j];
  }

  const float SCALE = 0.42044820762685725f;   // 32^(-1/4)
#pragma unroll
  for (int i = 0; i < 8; i++) {
    float m = -1e30f;
#pragma unroll
    for (int j = 0; j < 8; j++) {
      float s = acc[i][j] * SCALE;
      acc[i][j] = s;
      m = fmaxf(m, s);
    }
    m = fmaxf(m, __shfl_xor_sync(0xffffffffu, m, 8));
    m = fmaxf(m, __shfl_xor_sync(0xffffffffu, m, 4));
    m = fmaxf(m, __shfl_xor_sync(0xffffffffu, m, 2));
    m = fmaxf(m, __shfl_xor_sync(0xffffffffu, m, 1));
    float sum = 0.f;
#pragma unroll
    for (int j = 0; j < 8; j++) {
      float e = __expf(acc[i][j] - m);
      acc[i][j] = e;
      sum += e;
    }
    sum += __shfl_xor_sync(0xffffffffu, sum, 8);
    sum += __shfl_xor_sync(0xffffffffu, sum, 4);
    sum += __shfl_xor_sync(0xffffffffu, sum, 2);
    sum += __shfl_xor_sync(0xffffffffu, sum, 1);
    float r = 1.0f / sum;
#pragma unroll
    for (int j = 0; j < 8; j++) acc[i][j] *= r;
  }

  __syncthreads();

#pragma unroll
  for (int i = 0; i < 8; i++)
#pragma unroll
    for (int j = 0; j < 8; j++)
      QT[(tx * 8 + j) * 132 + ty * 8 + i] = acc[i][j];

  for (int e = tid; e < NHW; e += 256) {
    int r = e >> 7;
    int w = e & 127;
    KT[r * 132 + w] = gv[base + e];
  }
  __syncthreads();

#pragma unroll
  for (int i = 0; i < 8; i++)
#pragma unroll
    for (int j = 0; j < 8; j++) acc[i][j] = 0.f;

#pragma unroll 4
  for (int y = 0; y < 128; y++) {
    float a[8], bb[8];
    *(float4*)(a)      = *(const float4*)(&QT[y * 132 + ty * 8]);
    *(float4*)(a + 4)  = *(const float4*)(&QT[y * 132 + ty * 8 + 4]);
    *(float4*)(bb)     = *(const float4*)(&KT[y * 132 + tx * 8]);
    *(float4*)(bb + 4) = *(const float4*)(&KT[y * 132 + tx * 8 + 4]);
#pragma unroll
    for (int i = 0; i < 8; i++)
#pragma unroll
      for (int j = 0; j < 8; j++) acc[i][j] += a[i] * bb[j];
  }

#pragma unroll
  for (int i = 0; i < 8; i++) {
    float* dst = go + base + (size_t)(ty * 8 + i) * NW + tx * 8;
    *(float4*)(dst)     = make_float4(acc[i][0], acc[i][1], acc[i][2], acc[i][3]);
    *(float4*)(dst + 4) = make_float4(acc[i][4], acc[i][5], acc[i][6], acc[i][7]);
  }
}

// ---------------------------------------------------------------------------
extern "C" void kernel_launch(void* const* d_in, const int* in_sizes, int n_in,
                              void* d_out, int out_size) {
  const float* x  = (const float*)d_in[0];
  const float* wq = (const float*)d_in[1];
  const float* bq = (const float*)d_in[2];
  const float* wk = (const float*)d_in[3];
  const float* bk = (const float*)d_in[4];
  const float* wv = (const float*)d_in[5];
  const float* bv = (const float*)d_in[6];
  const float* wo = (const float*)d_in[7];
  const float* bo = (const float*)d_in[8];

  float *q, *k, *v, *att;
  __nv_bfloat16 *xh, *xl, *wh, *wl;
  cudaGetSymbolAddress((void**)&q,   g_q);
  cudaGetSymbolAddress((void**)&k,   g_k);
  cudaGetSymbolAddress((void**)&v,   g_v);
  cudaGetSymbolAddress((void**)&att, g_att);
  cudaGetSymbolAddress((void**)&xh,  g_x_hi);
  cudaGetSymbolAddress((void**)&xl,  g_x_lo);
  cudaGetSymbolAddress((void**)&wh,  g_w_hi);
  cudaGetSymbolAddress((void**)&wl,  g_w_lo);

  const int SMEM_ATTN = 2 * 128 * 132 * sizeof(float);   // 135168 B
  cudaFuncSetAttribute(attn_kernel,
                       cudaFuncAttributeMaxDynamicSharedMemorySize, SMEM_ATTN);
  cudaFuncSetAttribute(gemm_mma,
                       cudaFuncAttributeMaxDynamicSharedMemorySize, SMEM_GEMM);

  const int NTOT4 = NB * NC * NHW / 4;   // float4 count

  // Conversions
  split_f32<<<NTOT4 / 256, 256>>>(x, xh, xl);
  convert_w<<<dim3(NC * NC / 256, 4), 256>>>(wq, wk, wv, wo, wh, wl);

  // QKV projections on tensor cores (mma.sync bf16-split)
  dim3 ggrid(NHW / 128, NC / 128, NB);
  gemm_mma<<<ggrid, 256, SMEM_GEMM>>>(xh, xl, wh + 0 * NC * NC, wl + 0 * NC * NC, bq, q);
  gemm_mma<<<ggrid, 256, SMEM_GEMM>>>(xh, xl, wh + 1 * NC * NC, wl + 1 * NC * NC, bk, k);
  gemm_mma<<<ggrid, 256, SMEM_GEMM>>>(xh, xl, wh + 2 * NC * NC, wl + 2 * NC * NC, bv, v);

  // Attention
  attn_kernel<<<NB * NC, 256, SMEM_ATTN>>>(q, k, v, att);

  // Output projection
  split_f32<<<NTOT4 / 256, 256>>>(att, xh, xl);
  gemm_mma<<<ggrid, 256, SMEM_GEMM>>>(xh, xl, wh + 3 * NC * NC, wl + 3 * NC * NC, bo,
                                      (float*)d_out);
}

// round 4
// speedup vs baseline: 2.1350x; 1.3577x over previous
#include <cuda_runtime.h>
#include <cuda_bf16.h>
#include <cstdint>
#include <math.h>

#define NB   8
#define NC   256
#define NH   128
#define NW   128
#define NHW  (NH * NW)        // 16384

// ---------------------------------------------------------------------------
// Scratch (device globals: allocation-guard safe)
// ---------------------------------------------------------------------------
__device__ __nv_bfloat16 g_x_hi[(size_t)NB * NC * NHW];      // [b][c][n]
__device__ __nv_bfloat16 g_x_lo[(size_t)NB * NC * NHW];
__device__ __nv_bfloat16 g_qkv_hi[(size_t)NB * 3 * NC * NHW]; // [b][3C][n]
__device__ __nv_bfloat16 g_qkv_lo[(size_t)NB * 3 * NC * NHW];
__device__ __nv_bfloat16 g_att_hi[(size_t)NB * NC * NHW];
__device__ __nv_bfloat16 g_att_lo[(size_t)NB * NC * NHW];
__device__ __nv_bfloat16 g_w_hi[4 * NC * NC];                // wq,wk,wv,wo [o][c]
__device__ __nv_bfloat16 g_w_lo[4 * NC * NC];
__device__ float g_bias[4 * NC];

// ---------------------------------------------------------------------------
// PTX helpers (sm_80-baseline tensor core path; valid on compute_103)
// ---------------------------------------------------------------------------
__device__ __forceinline__ uint32_t smem_u32(const void* p) {
  uint32_t a;
  asm("{ .reg .u64 t; cvta.to.shared.u64 t, %1; cvt.u32.u64 %0, t; }"
      : "=r"(a) : "l"(p));
  return a;
}
__device__ __forceinline__ void cp_async16(uint32_t sdst, const void* gsrc) {
  asm volatile("cp.async.cg.shared.global [%0], [%1], 16;"
               :: "r"(sdst), "l"(gsrc));
}
#define CP_COMMIT() asm volatile("cp.async.commit_group;" ::: "memory")
#define CP_WAIT0()  asm volatile("cp.async.wait_group 0;" ::: "memory")

__device__ __forceinline__ void ldsm_x4(uint32_t* r, uint32_t addr) {
  asm volatile("ldmatrix.sync.aligned.m8n8.x4.shared.b16 {%0,%1,%2,%3}, [%4];"
               : "=r"(r[0]), "=r"(r[1]), "=r"(r[2]), "=r"(r[3]) : "r"(addr));
}
__device__ __forceinline__ void ldsm_x4_t(uint32_t* r, uint32_t addr) {
  asm volatile("ldmatrix.sync.aligned.m8n8.x4.trans.shared.b16 {%0,%1,%2,%3}, [%4];"
               : "=r"(r[0]), "=r"(r[1]), "=r"(r[2]), "=r"(r[3]) : "r"(addr));
}
__device__ __forceinline__ void mma_bf16(float* d, const uint32_t* a,
                                         uint32_t b0, uint32_t b1) {
  asm volatile(
      "mma.sync.aligned.m16n8k16.row.col.f32.bf16.bf16.f32 "
      "{%0,%1,%2,%3}, {%4,%5,%6,%7}, {%8,%9}, {%0,%1,%2,%3};"
      : "+f"(d[0]), "+f"(d[1]), "+f"(d[2]), "+f"(d[3])
      : "r"(a[0]), "r"(a[1]), "r"(a[2]), "r"(a[3]), "r"(b0), "r"(b1));
}
__device__ __forceinline__ uint32_t pack_hi(float a, float b) {
  __nv_bfloat162 p = {__float2bfloat16(a), __float2bfloat16(b)};
  return *(uint32_t*)&p;
}
__device__ __forceinline__ uint32_t pack_lo(float a, float b) {
  __nv_bfloat16 ha = __float2bfloat16(a), hb = __float2bfloat16(b);
  __nv_bfloat162 p = {__float2bfloat16(a - __bfloat162float(ha)),
                      __float2bfloat16(b - __bfloat162float(hb))};
  return *(uint32_t*)&p;
}

// ---------------------------------------------------------------------------
// Elementwise bf16 split: fp32 -> hi + lo (same layout)
// ---------------------------------------------------------------------------
__global__ __launch_bounds__(256) void split_f32(
    const float* __restrict__ X, __nv_bfloat16* __restrict__ H,
    __nv_bfloat16* __restrict__ L) {
  int i = blockIdx.x * 256 + threadIdx.x;
  float4 v = ((const float4*)X)[i];
  ((uint2*)H)[i] = make_uint2(pack_hi(v.x, v.y), pack_hi(v.z, v.w));
  ((uint2*)L)[i] = make_uint2(pack_lo(v.x, v.y), pack_lo(v.z, v.w));
}

__global__ __launch_bounds__(256) void convert_w(
    const float* __restrict__ w0, const float* __restrict__ w1,
    const float* __restrict__ w2, const float* __restrict__ w3,
    const float* __restrict__ b0, const float* __restrict__ b1,
    const float* __restrict__ b2, const float* __restrict__ b3,
    __nv_bfloat16* __restrict__ H, __nv_bfloat16* __restrict__ L) {
  const float* ws[4] = {w0, w1, w2, w3};
  const float* bs[4] = {b0, b1, b2, b3};
  int m = blockIdx.y;
  int i = blockIdx.x * 256 + threadIdx.x;
  float v = ws[m][i];
  __nv_bfloat16 h = __float2bfloat16(v);
  H[m * NC * NC + i] = h;
  L[m * NC * NC + i] = __float2bfloat16(v - __bfloat162float(h));
  if (blockIdx.x == 0) g_bias[m * NC + threadIdx.x] = bs[m][threadIdx.x];
}

// ---------------------------------------------------------------------------
// mma.sync bf16-split GEMM: D[o][n] = sum_c W[o][c] * X[c][n] + bias[o]
// CTA 128x128, K chunks 32, double-buffered cp.async, 8 warps (4 o x 2 n).
// Output: fp32 (final) OR bf16 hi/lo (intermediate).
// ---------------------------------------------------------------------------
#define OFF_AH   0
#define OFF_AL   10240                 // 128*80
#define OFF_BH   20480
#define OFF_BL   29184                 // + 32*272
#define BUF_BYTES 37888
#define SMEM_GEMM (2 * BUF_BYTES)

__global__ __launch_bounds__(256) void gemm_mma(
    const __nv_bfloat16* __restrict__ Xh, const __nv_bfloat16* __restrict__ Xl,
    const __nv_bfloat16* __restrict__ Wh, const __nv_bfloat16* __restrict__ Wl,
    const float* __restrict__ bias, float* __restrict__ Yf,
    __nv_bfloat16* __restrict__ Yh, __nv_bfloat16* __restrict__ Yl,
    int ocnt) {
  extern __shared__ __align__(16) char sm[];
  const uint32_t smb = smem_u32(sm);

  const int tid  = threadIdx.x;
  const int lane = tid & 31;
  const int wid  = tid >> 5;
  const int wm   = wid & 3;
  const int wn   = wid >> 2;
  const int b    = blockIdx.z;
  const int n0   = blockIdx.x * 128;
  const int o0   = blockIdx.y * 128;

  const __nv_bfloat16* Xbh = Xh + (size_t)b * NC * NHW + n0;
  const __nv_bfloat16* Xbl = Xl + (size_t)b * NC * NHW + n0;
  const __nv_bfloat16* Wbh = Wh + (size_t)o0 * NC;
  const __nv_bfloat16* Wbl = Wl + (size_t)o0 * NC;

  const int a_row0 = tid >> 2, a_seg = tid & 3;
  const int b_row0 = tid >> 4, b_seg = tid & 15;

  float acc[2][8][4];
#pragma unroll
  for (int mt = 0; mt < 2; mt++)
#pragma unroll
    for (int nt = 0; nt < 8; nt++)
#pragma unroll
      for (int e = 0; e < 4; e++) acc[mt][nt][e] = 0.f;

  const int lr = lane & 15, lc = lane >> 4;
  uint32_t a_base = (uint32_t)((wm * 32 + lr) * 80 + lc * 16);
  uint32_t b_base = (uint32_t)(lr * 272 + wn * 128 + lc * 16);

  auto stage = [&](int it) {
    const int c0 = it * 32;
    const uint32_t sb = smb + (it & 1) * BUF_BYTES;
#pragma unroll
    for (int r = 0; r < 2; r++) {
      int row = a_row0 + r * 64;
      uint32_t so = (uint32_t)(row * 80 + a_seg * 16);
      cp_async16(sb + OFF_AH + so, Wbh + (size_t)row * NC + c0 + a_seg * 8);
      cp_async16(sb + OFF_AL + so, Wbl + (size_t)row * NC + c0 + a_seg * 8);
    }
#pragma unroll
    for (int r = 0; r < 2; r++) {
      int row = b_row0 + r * 16;
      uint32_t so = (uint32_t)(row * 272 + b_seg * 16);
      cp_async16(sb + OFF_BH + so, Xbh + (size_t)(c0 + row) * NHW + b_seg * 8);
      cp_async16(sb + OFF_BL + so, Xbl + (size_t)(c0 + row) * NHW + b_seg * 8);
    }
    CP_COMMIT();
  };

  stage(0);

  for (int it = 0; it < 8; it++) {
    CP_WAIT0();
    __syncthreads();
    if (it + 1 < 8) stage(it + 1);

    const uint32_t sb = smb + (it & 1) * BUF_BYTES;
#pragma unroll
    for (int ks = 0; ks < 2; ks++) {
      uint32_t ah[2][4], al[2][4];
#pragma unroll
      for (int mt = 0; mt < 2; mt++) {
        uint32_t ao = sb + a_base + (uint32_t)(mt * 16 * 80 + ks * 32);
        ldsm_x4(ah[mt], ao + OFF_AH);
        ldsm_x4(al[mt], ao + OFF_AL);
      }
#pragma unroll
      for (int nt2 = 0; nt2 < 4; nt2++) {
        uint32_t bh[4], bl[4];
        uint32_t bo = sb + b_base + (uint32_t)(ks * 16 * 272 + nt2 * 32);
        ldsm_x4_t(bh, bo + OFF_BH);
        ldsm_x4_t(bl, bo + OFF_BL);
#pragma unroll
        for (int mt = 0; mt < 2; mt++) {
          mma_bf16(acc[mt][nt2 * 2],     ah[mt], bh[0], bh[1]);
          mma_bf16(acc[mt][nt2 * 2 + 1], ah[mt], bh[2], bh[3]);
          mma_bf16(acc[mt][nt2 * 2],     ah[mt], bl[0], bl[1]);
          mma_bf16(acc[mt][nt2 * 2 + 1], ah[mt], bl[2], bl[3]);
          mma_bf16(acc[mt][nt2 * 2],     al[mt], bh[0], bh[1]);
          mma_bf16(acc[mt][nt2 * 2 + 1], al[mt], bh[2], bh[3]);
        }
      }
    }
    __syncthreads();
  }

#pragma unroll
  for (int mt = 0; mt < 2; mt++) {
    int o = o0 + wm * 32 + mt * 16 + (lane >> 2);
    float bv0 = __ldg(bias + o);
    float bv1 = __ldg(bias + o + 8);
#pragma unroll
    for (int nt = 0; nt < 8; nt++) {
      int n = n0 + wn * 64 + nt * 8 + (lane & 3) * 2;
      float v00 = acc[mt][nt][0] + bv0, v01 = acc[mt][nt][1] + bv0;
      float v10 = acc[mt][nt][2] + bv1, v11 = acc[mt][nt][3] + bv1;
      size_t off0 = ((size_t)b * ocnt + o) * NHW + n;
      size_t off1 = ((size_t)b * ocnt + o + 8) * NHW + n;
      if (Yf) {
        *(float2*)(Yf + off0) = make_float2(v00, v01);
        *(float2*)(Yf + off1) = make_float2(v10, v11);
      } else {
        *(uint32_t*)(Yh + off0) = pack_hi(v00, v01);
        *(uint32_t*)(Yh + off1) = pack_hi(v10, v11);
        *(uint32_t*)(Yl + off0) = pack_lo(v00, v01);
        *(uint32_t*)(Yl + off1) = pack_lo(v10, v11);
      }
    }
  }
}

// ---------------------------------------------------------------------------
// Tensor-core attention: one CTA per (b, c) slice.
// SMEM (206848 B): [Qh|Ql|Kh|Kl] (4 x 34816, stride 272B) + S fp32 (128x132).
// Reuse after S: Q->P(hi/lo), K->V(hi/lo).
// ---------------------------------------------------------------------------
#define AOFF_QH 0
#define AOFF_QL 34816
#define AOFF_KH 69632
#define AOFF_KL 104448
#define AOFF_S  139264
#define SMEM_ATTN (139264 + 128 * 528)     // 206848

__global__ __launch_bounds__(256) void attn_mma(
    const __nv_bfloat16* __restrict__ QKVh,
    const __nv_bfloat16* __restrict__ QKVl,
    __nv_bfloat16* __restrict__ Oh, __nv_bfloat16* __restrict__ Ol) {
  extern __shared__ __align__(16) char sm[];
  const uint32_t smb = smem_u32(sm);
  float* Sf = (float*)(sm + AOFF_S);

  const int tid  = threadIdx.x;
  const int lane = tid & 31;
  const int wid  = tid >> 5;
  const int wm   = wid & 3;
  const int wn   = wid >> 2;

  const int b = blockIdx.x >> 8;
  const int c = blockIdx.x & 255;
  const size_t qb = ((size_t)b * 3 * NC + c) * NHW;
  const size_t kb = qb + (size_t)NC * NHW;
  const size_t vb = qb + (size_t)2 * NC * NHW;

  // Stage Q,K (hi+lo): 128 rows x 16 segs of 16B each
  const int srow = tid >> 4, sseg = tid & 15;
#pragma unroll
  for (int r = 0; r < 8; r++) {
    int row = srow + r * 16;
    uint32_t so = (uint32_t)(row * 272 + sseg * 16);
    const __nv_bfloat16* gq = QKVh + qb + row * 128 + sseg * 8;
    cp_async16(smb + AOFF_QH + so, gq);
    cp_async16(smb + AOFF_QL + so, QKVl + qb + row * 128 + sseg * 8);
    cp_async16(smb + AOFF_KH + so, QKVh + kb + row * 128 + sseg * 8);
    cp_async16(smb + AOFF_KL + so, QKVl + kb + row * 128 + sseg * 8);
  }
  CP_COMMIT();
  CP_WAIT0();
  __syncthreads();

  const int lr = lane & 15, lc = lane >> 4;
  float acc[2][8][4];
#pragma unroll
  for (int mt = 0; mt < 2; mt++)
#pragma unroll
    for (int nt = 0; nt < 8; nt++)
#pragma unroll
      for (int e = 0; e < 4; e++) acc[mt][nt][e] = 0.f;

  // S = Q K^T  (A: rows x, k=w contiguous; B: rows y, k=w contiguous -> non-trans)
#pragma unroll
  for (int ks = 0; ks < 8; ks++) {
    uint32_t ah[2][4], al[2][4];
#pragma unroll
    for (int mt = 0; mt < 2; mt++) {
      uint32_t ao = smb + (uint32_t)((wm * 32 + mt * 16 + lr) * 272 + ks * 32 + lc * 16);
      ldsm_x4(ah[mt], ao + AOFF_QH);
      ldsm_x4(al[mt], ao + AOFF_QL);
    }
#pragma unroll
    for (int nt2 = 0; nt2 < 4; nt2++) {
      uint32_t kh[4], kl[4];
      uint32_t bo = smb + (uint32_t)((wn * 64 + nt2 * 16 + lr) * 272 + ks * 32 + lc * 16);
      ldsm_x4(kh, bo + AOFF_KH);
      ldsm_x4(kl, bo + AOFF_KL);
#pragma unroll
      for (int mt = 0; mt < 2; mt++) {
        // n-tile pairs: {r0,r2} (n 0-7), {r1,r3} (n 8-15)
        mma_bf16(acc[mt][nt2 * 2],     ah[mt], kh[0], kh[2]);
        mma_bf16(acc[mt][nt2 * 2 + 1], ah[mt], kh[1], kh[3]);
        mma_bf16(acc[mt][nt2 * 2],     ah[mt], kl[0], kl[2]);
        mma_bf16(acc[mt][nt2 * 2 + 1], ah[mt], kl[1], kl[3]);
        mma_bf16(acc[mt][nt2 * 2],     al[mt], kh[0], kh[2]);
        mma_bf16(acc[mt][nt2 * 2 + 1], al[mt], kh[1], kh[3]);
      }
    }
  }

  // Write scaled S to smem fp32 [x][y], stride 132 floats
  const float SCALE = 0.42044820762685725f;   // 32^(-1/4)
#pragma unroll
  for (int mt = 0; mt < 2; mt++) {
    int row = wm * 32 + mt * 16 + (lane >> 2);
#pragma unroll
    for (int nt = 0; nt < 8; nt++) {
      int col = wn * 64 + nt * 8 + (lane & 3) * 2;
      *(float2*)(&Sf[row * 132 + col]) =
          make_float2(acc[mt][nt][0] * SCALE, acc[mt][nt][1] * SCALE);
      *(float2*)(&Sf[(row + 8) * 132 + col]) =
          make_float2(acc[mt][nt][2] * SCALE, acc[mt][nt][3] * SCALE);
    }
  }
  __syncthreads();   // all S written; all K reads done

  // Kick off V load into K region (overlaps softmax)
#pragma unroll
  for (int r = 0; r < 8; r++) {
    int row = srow + r * 16;
    uint32_t so = (uint32_t)(row * 272 + sseg * 16);
    cp_async16(smb + AOFF_KH + so, QKVh + vb + row * 128 + sseg * 8);
    cp_async16(smb + AOFF_KL + so, QKVl + vb + row * 128 + sseg * 8);
  }
  CP_COMMIT();

  // Softmax: each warp owns 16 rows; lane covers 4 cols
  __nv_bfloat16* Ph = (__nv_bfloat16*)(sm + AOFF_QH);
  __nv_bfloat16* Pl = (__nv_bfloat16*)(sm + AOFF_QL);
#pragma unroll
  for (int i = 0; i < 16; i++) {
    int r = wid * 16 + i;
    float4 v = *(float4*)(&Sf[r * 132 + lane * 4]);
    float m = fmaxf(fmaxf(v.x, v.y), fmaxf(v.z, v.w));
    m = fmaxf(m, __shfl_xor_sync(0xffffffffu, m, 16));
    m = fmaxf(m, __shfl_xor_sync(0xffffffffu, m, 8));
    m = fmaxf(m, __shfl_xor_sync(0xffffffffu, m, 4));
    m = fmaxf(m, __shfl_xor_sync(0xffffffffu, m, 2));
    m = fmaxf(m, __shfl_xor_sync(0xffffffffu, m, 1));
    float e0 = __expf(v.x - m), e1 = __expf(v.y - m);
    float e2 = __expf(v.z - m), e3 = __expf(v.w - m);
    float s = e0 + e1 + e2 + e3;
    s += __shfl_xor_sync(0xffffffffu, s, 16);
    s += __shfl_xor_sync(0xffffffffu, s, 8);
    s += __shfl_xor_sync(0xffffffffu, s, 4);
    s += __shfl_xor_sync(0xffffffffu, s, 2);
    s += __shfl_xor_sync(0xffffffffu, s, 1);
    float rs = 1.0f / s;
    e0 *= rs; e1 *= rs; e2 *= rs; e3 *= rs;
    uint32_t base = (uint32_t)(r * 136 + lane * 4);   // elements
    *(uint2*)(Ph + base) = make_uint2(pack_hi(e0, e1), pack_hi(e2, e3));
    *(uint2*)(Pl + base) = make_uint2(pack_lo(e0, e1), pack_lo(e2, e3));
  }
  CP_WAIT0();
  __syncthreads();

  // O = P V  (A: P rows x, k=y contiguous; B: V rows y, cols w -> trans)
#pragma unroll
  for (int mt = 0; mt < 2; mt++)
#pragma unroll
    for (int nt = 0; nt < 8; nt++)
#pragma unroll
      for (int e = 0; e < 4; e++) acc[mt][nt][e] = 0.f;

#pragma unroll
  for (int ks = 0; ks < 8; ks++) {
    uint32_t ph[2][4], pl[2][4];
#pragma unroll
    for (int mt = 0; mt < 2; mt++) {
      uint32_t ao = smb + (uint32_t)((wm * 32 + mt * 16 + lr) * 272 + ks * 32 + lc * 16);
      ldsm_x4(ph[mt], ao + AOFF_QH);
      ldsm_x4(pl[mt], ao + AOFF_QL);
    }
#pragma unroll
    for (int nt2 = 0; nt2 < 4; nt2++) {
      uint32_t vh[4], vl[4];
      uint32_t bo = smb + (uint32_t)((ks * 16 + lr) * 272 + wn * 128 + nt2 * 32 + lc * 16);
      ldsm_x4_t(vh, bo + AOFF_KH);
      ldsm_x4_t(vl, bo + AOFF_KL);
#pragma unroll
      for (int mt = 0; mt < 2; mt++) {
        mma_bf16(acc[mt][nt2 * 2],     ph[mt], vh[0], vh[1]);
        mma_bf16(acc[mt][nt2 * 2 + 1], ph[mt], vh[2], vh[3]);
        mma_bf16(acc[mt][nt2 * 2],     ph[mt], vl[0], vl[1]);
        mma_bf16(acc[mt][nt2 * 2 + 1], ph[mt], vl[2], vl[3]);
        mma_bf16(acc[mt][nt2 * 2],     pl[mt], vh[0], vh[1]);
        mma_bf16(acc[mt][nt2 * 2 + 1], pl[mt], vh[2], vh[3]);
      }
    }
  }

  // Epilogue: write O hi/lo bf16 [b][c][x*128+w]
  const size_t ob = ((size_t)b * NC + c) * NHW;
#pragma unroll
  for (int mt = 0; mt < 2; mt++) {
    int row = wm * 32 + mt * 16 + (lane >> 2);
#pragma unroll
    for (int nt = 0; nt < 8; nt++) {
      int col = wn * 64 + nt * 8 + (lane & 3) * 2;
      size_t o0 = ob + (size_t)row * 128 + col;
      size_t o1 = ob + (size_t)(row + 8) * 128 + col;
      *(uint32_t*)(Oh + o0) = pack_hi(acc[mt][nt][0], acc[mt][nt][1]);
      *(uint32_t*)(Oh + o1) = pack_hi(acc[mt][nt][2], acc[mt][nt][3]);
      *(uint32_t*)(Ol + o0) = pack_lo(acc[mt][nt][0], acc[mt][nt][1]);
      *(uint32_t*)(Ol + o1) = pack_lo(acc[mt][nt][2], acc[mt][nt][3]);
    }
  }
}

// ---------------------------------------------------------------------------
extern "C" void kernel_launch(void* const* d_in, const int* in_sizes, int n_in,
                              void* d_out, int out_size) {
  const float* x  = (const float*)d_in[0];
  const float* wq = (const float*)d_in[1];
  const float* bq = (const float*)d_in[2];
  const float* wk = (const float*)d_in[3];
  const float* bk = (const float*)d_in[4];
  const float* wv = (const float*)d_in[5];
  const float* bv = (const float*)d_in[6];
  const float* wo = (const float*)d_in[7];
  const float* bo = (const float*)d_in[8];

  __nv_bfloat16 *xh, *xl, *qkvh, *qkvl, *ath, *atl, *wh, *wl;
  float* bias;
  cudaGetSymbolAddress((void**)&xh,   g_x_hi);
  cudaGetSymbolAddress((void**)&xl,   g_x_lo);
  cudaGetSymbolAddress((void**)&qkvh, g_qkv_hi);
  cudaGetSymbolAddress((void**)&qkvl, g_qkv_lo);
  cudaGetSymbolAddress((void**)&ath,  g_att_hi);
  cudaGetSymbolAddress((void**)&atl,  g_att_lo);
  cudaGetSymbolAddress((void**)&wh,   g_w_hi);
  cudaGetSymbolAddress((void**)&wl,   g_w_lo);
  cudaGetSymbolAddress((void**)&bias, g_bias);

  cudaFuncSetAttribute(gemm_mma,
                       cudaFuncAttributeMaxDynamicSharedMemorySize, SMEM_GEMM);
  cudaFuncSetAttribute(attn_mma,
                       cudaFuncAttributeMaxDynamicSharedMemorySize, SMEM_ATTN);

  // Convert inputs
  split_f32<<<NB * NC * NHW / 4 / 256, 256>>>(x, xh, xl);
  convert_w<<<dim3(NC * NC / 256, 4), 256>>>(wq, wk, wv, wo, bq, bk, bv, bo, wh, wl);

  // Fused QKV projection -> bf16 hi/lo
  gemm_mma<<<dim3(NHW / 128, 6, NB), 256, SMEM_GEMM>>>(
      xh, xl, wh, wl, bias, nullptr, qkvh, qkvl, 3 * NC);

  // Tensor-core attention -> bf16 hi/lo
  attn_mma<<<NB * NC, 256, SMEM_ATTN>>>(qkvh, qkvl, ath, atl);

  // Output projection -> fp32 d_out
  gemm_mma<<<dim3(NHW / 128, 2, NB), 256, SMEM_GEMM>>>(
      ath, atl, wh + 3 * NC * NC, wl + 3 * NC * NC, bias + 3 * NC,
      (float*)d_out, nullptr, nullptr, NC);
}

// round 5
// speedup vs baseline: 2.6135x; 1.2241x over previous
#include <cuda_runtime.h>
#include <cuda_bf16.h>
#include <cstdint>
#include <math.h>

#define NB   8
#define NC   256
#define NH   128
#define NW   128
#define NHW  (NH * NW)        // 16384

// ---------------------------------------------------------------------------
// Scratch (device globals: allocation-guard safe)
// ---------------------------------------------------------------------------
__device__ __nv_bfloat16 g_x_hi[(size_t)NB * NC * NHW];      // [b][c][n]
__device__ __nv_bfloat16 g_x_lo[(size_t)NB * NC * NHW];
__device__ __nv_bfloat16 g_qkv_hi[(size_t)NB * 3 * NC * NHW]; // [b][3C][n]
__device__ __nv_bfloat16 g_qkv_lo[(size_t)NB * 3 * NC * NHW];
__device__ __nv_bfloat16 g_att_hi[(size_t)NB * NC * NHW];
__device__ __nv_bfloat16 g_att_lo[(size_t)NB * NC * NHW];
__device__ __nv_bfloat16 g_w_hi[4 * NC * NC];                // wq,wk,wv,wo [o][c]
__device__ __nv_bfloat16 g_w_lo[4 * NC * NC];
__device__ float g_bias[4 * NC];

// ---------------------------------------------------------------------------
// PTX helpers (sm_80-baseline tensor core path; valid on compute_103)
// ---------------------------------------------------------------------------
__device__ __forceinline__ uint32_t smem_u32(const void* p) {
  uint32_t a;
  asm("{ .reg .u64 t; cvta.to.shared.u64 t, %1; cvt.u32.u64 %0, t; }"
      : "=r"(a) : "l"(p));
  return a;
}
__device__ __forceinline__ void cp_async16(uint32_t sdst, const void* gsrc) {
  asm volatile("cp.async.cg.shared.global [%0], [%1], 16;"
               :: "r"(sdst), "l"(gsrc));
}
#define CP_COMMIT() asm volatile("cp.async.commit_group;" ::: "memory")
#define CP_WAIT0()  asm volatile("cp.async.wait_group 0;" ::: "memory")
#define CP_WAIT1()  asm volatile("cp.async.wait_group 1;" ::: "memory")

__device__ __forceinline__ void ldsm_x4(uint32_t* r, uint32_t addr) {
  asm volatile("ldmatrix.sync.aligned.m8n8.x4.shared.b16 {%0,%1,%2,%3}, [%4];"
               : "=r"(r[0]), "=r"(r[1]), "=r"(r[2]), "=r"(r[3]) : "r"(addr));
}
__device__ __forceinline__ void ldsm_x4_t(uint32_t* r, uint32_t addr) {
  asm volatile("ldmatrix.sync.aligned.m8n8.x4.trans.shared.b16 {%0,%1,%2,%3}, [%4];"
               : "=r"(r[0]), "=r"(r[1]), "=r"(r[2]), "=r"(r[3]) : "r"(addr));
}
__device__ __forceinline__ void mma_bf16(float* d, const uint32_t* a,
                                         uint32_t b0, uint32_t b1) {
  asm volatile(
      "mma.sync.aligned.m16n8k16.row.col.f32.bf16.bf16.f32 "
      "{%0,%1,%2,%3}, {%4,%5,%6,%7}, {%8,%9}, {%0,%1,%2,%3};"
      : "+f"(d[0]), "+f"(d[1]), "+f"(d[2]), "+f"(d[3])
      : "r"(a[0]), "r"(a[1]), "r"(a[2]), "r"(a[3]), "r"(b0), "r"(b1));
}
__device__ __forceinline__ uint32_t pack_hi(float a, float b) {
  __nv_bfloat162 p = {__float2bfloat16(a), __float2bfloat16(b)};
  return *(uint32_t*)&p;
}
__device__ __forceinline__ uint32_t pack_lo(float a, float b) {
  __nv_bfloat16 ha = __float2bfloat16(a), hb = __float2bfloat16(b);
  __nv_bfloat162 p = {__float2bfloat16(a - __bfloat162float(ha)),
                      __float2bfloat16(b - __bfloat162float(hb))};
  return *(uint32_t*)&p;
}

// ---------------------------------------------------------------------------
// Elementwise bf16 split: fp32 -> hi + lo (same layout)
// ---------------------------------------------------------------------------
__global__ __launch_bounds__(256) void split_f32(
    const float* __restrict__ X, __nv_bfloat16* __restrict__ H,
    __nv_bfloat16* __restrict__ L) {
  int i = blockIdx.x * 256 + threadIdx.x;
  float4 v = ((const float4*)X)[i];
  ((uint2*)H)[i] = make_uint2(pack_hi(v.x, v.y), pack_hi(v.z, v.w));
  ((uint2*)L)[i] = make_uint2(pack_lo(v.x, v.y), pack_lo(v.z, v.w));
}

__global__ __launch_bounds__(256) void convert_w(
    const float* __restrict__ w0, const float* __restrict__ w1,
    const float* __restrict__ w2, const float* __restrict__ w3,
    const float* __restrict__ b0, const float* __restrict__ b1,
    const float* __restrict__ b2, const float* __restrict__ b3,
    __nv_bfloat16* __restrict__ H, __nv_bfloat16* __restrict__ L) {
  const float* ws[4] = {w0, w1, w2, w3};
  const float* bs[4] = {b0, b1, b2, b3};
  int m = blockIdx.y;
  int i = blockIdx.x * 256 + threadIdx.x;
  float v = ws[m][i];
  __nv_bfloat16 h = __float2bfloat16(v);
  H[m * NC * NC + i] = h;
  L[m * NC * NC + i] = __float2bfloat16(v - __bfloat162float(h));
  if (blockIdx.x == 0) g_bias[m * NC + threadIdx.x] = bs[m][threadIdx.x];
}

// ---------------------------------------------------------------------------
// mma.sync bf16-split GEMM: D[o][n] = sum_c W[o][c] * X[c][n] + bias[o]
// CTA 128x128, K chunks 32, double-buffered cp.async, 8 warps (4 o x 2 n).
// launch_bounds(256,2): cap regs at 128 so 2 CTAs/SM reside (reg-file limit).
// ---------------------------------------------------------------------------
#define OFF_AH   0
#define OFF_AL   10240                 // 128*80
#define OFF_BH   20480
#define OFF_BL   29184                 // + 32*272
#define BUF_BYTES 37888
#define SMEM_GEMM (2 * BUF_BYTES)

__global__ __launch_bounds__(256, 2) void gemm_mma(
    const __nv_bfloat16* __restrict__ Xh, const __nv_bfloat16* __restrict__ Xl,
    const __nv_bfloat16* __restrict__ Wh, const __nv_bfloat16* __restrict__ Wl,
    const float* __restrict__ bias, float* __restrict__ Yf,
    __nv_bfloat16* __restrict__ Yh, __nv_bfloat16* __restrict__ Yl,
    int ocnt) {
  extern __shared__ __align__(16) char sm[];
  const uint32_t smb = smem_u32(sm);

  const int tid  = threadIdx.x;
  const int lane = tid & 31;
  const int wid  = tid >> 5;
  const int wm   = wid & 3;
  const int wn   = wid >> 2;
  const int b    = blockIdx.z;
  const int n0   = blockIdx.x * 128;
  const int o0   = blockIdx.y * 128;

  const __nv_bfloat16* Xbh = Xh + (size_t)b * NC * NHW + n0;
  const __nv_bfloat16* Xbl = Xl + (size_t)b * NC * NHW + n0;
  const __nv_bfloat16* Wbh = Wh + (size_t)o0 * NC;
  const __nv_bfloat16* Wbl = Wl + (size_t)o0 * NC;

  const int a_row0 = tid >> 2, a_seg = tid & 3;
  const int b_row0 = tid >> 4, b_seg = tid & 15;

  float acc[2][8][4];
#pragma unroll
  for (int mt = 0; mt < 2; mt++)
#pragma unroll
    for (int nt = 0; nt < 8; nt++)
#pragma unroll
      for (int e = 0; e < 4; e++) acc[mt][nt][e] = 0.f;

  const int lr = lane & 15, lc = lane >> 4;
  uint32_t a_base = (uint32_t)((wm * 32 + lr) * 80 + lc * 16);
  uint32_t b_base = (uint32_t)(lr * 272 + wn * 128 + lc * 16);

  auto stage = [&](int it) {
    const int c0 = it * 32;
    const uint32_t sb = smb + (it & 1) * BUF_BYTES;
#pragma unroll
    for (int r = 0; r < 2; r++) {
      int row = a_row0 + r * 64;
      uint32_t so = (uint32_t)(row * 80 + a_seg * 16);
      cp_async16(sb + OFF_AH + so, Wbh + (size_t)row * NC + c0 + a_seg * 8);
      cp_async16(sb + OFF_AL + so, Wbl + (size_t)row * NC + c0 + a_seg * 8);
    }
#pragma unroll
    for (int r = 0; r < 2; r++) {
      int row = b_row0 + r * 16;
      uint32_t so = (uint32_t)(row * 272 + b_seg * 16);
      cp_async16(sb + OFF_BH + so, Xbh + (size_t)(c0 + row) * NHW + b_seg * 8);
      cp_async16(sb + OFF_BL + so, Xbl + (size_t)(c0 + row) * NHW + b_seg * 8);
    }
    CP_COMMIT();
  };

  stage(0);

  for (int it = 0; it < 8; it++) {
    CP_WAIT0();
    __syncthreads();
    if (it + 1 < 8) stage(it + 1);

    const uint32_t sb = smb + (it & 1) * BUF_BYTES;
#pragma unroll
    for (int ks = 0; ks < 2; ks++) {
      uint32_t ah[2][4], al[2][4];
#pragma unroll
      for (int mt = 0; mt < 2; mt++) {
        uint32_t ao = sb + a_base + (uint32_t)(mt * 16 * 80 + ks * 32);
        ldsm_x4(ah[mt], ao + OFF_AH);
        ldsm_x4(al[mt], ao + OFF_AL);
      }
#pragma unroll
      for (int nt2 = 0; nt2 < 4; nt2++) {
        uint32_t bh[4], bl[4];
        uint32_t bo = sb + b_base + (uint32_t)(ks * 16 * 272 + nt2 * 32);
        ldsm_x4_t(bh, bo + OFF_BH);
        ldsm_x4_t(bl, bo + OFF_BL);
#pragma unroll
        for (int mt = 0; mt < 2; mt++) {
          mma_bf16(acc[mt][nt2 * 2],     ah[mt], bh[0], bh[1]);
          mma_bf16(acc[mt][nt2 * 2 + 1], ah[mt], bh[2], bh[3]);
          mma_bf16(acc[mt][nt2 * 2],     ah[mt], bl[0], bl[1]);
          mma_bf16(acc[mt][nt2 * 2 + 1], ah[mt], bl[2], bl[3]);
          mma_bf16(acc[mt][nt2 * 2],     al[mt], bh[0], bh[1]);
          mma_bf16(acc[mt][nt2 * 2 + 1], al[mt], bh[2], bh[3]);
        }
      }
    }
    __syncthreads();
  }

#pragma unroll
  for (int mt = 0; mt < 2; mt++) {
    int o = o0 + wm * 32 + mt * 16 + (lane >> 2);
    float bv0 = __ldg(bias + o);
    float bv1 = __ldg(bias + o + 8);
#pragma unroll
    for (int nt = 0; nt < 8; nt++) {
      int n = n0 + wn * 64 + nt * 8 + (lane & 3) * 2;
      float v00 = acc[mt][nt][0] + bv0, v01 = acc[mt][nt][1] + bv0;
      float v10 = acc[mt][nt][2] + bv1, v11 = acc[mt][nt][3] + bv1;
      size_t off0 = ((size_t)b * ocnt + o) * NHW + n;
      size_t off1 = ((size_t)b * ocnt + o + 8) * NHW + n;
      if (Yf) {
        *(float2*)(Yf + off0) = make_float2(v00, v01);
        *(float2*)(Yf + off1) = make_float2(v10, v11);
      } else {
        *(uint32_t*)(Yh + off0) = pack_hi(v00, v01);
        *(uint32_t*)(Yh + off1) = pack_hi(v10, v11);
        *(uint32_t*)(Yl + off0) = pack_lo(v00, v01);
        *(uint32_t*)(Yl + off1) = pack_lo(v10, v11);
      }
    }
  }
}

// ---------------------------------------------------------------------------
// Tensor-core attention v2: one CTA per (b, c) slice; warp-owned rows.
// Each warp computes 16 full rows of S (16x128) -> register softmax ->
// in-register P fragments -> P*V. S and P never touch smem.
// SMEM: Q,K,V hi/lo, 272B row stride (conflict-free ldmatrix), 208896 B.
// ---------------------------------------------------------------------------
#define AT_QH 0
#define AT_QL 34816
#define AT_KH 69632
#define AT_KL 104448
#define AT_VH 139264
#define AT_VL 174080
#define SMEM_ATTN2 208896

__global__ __launch_bounds__(256) void attn_mma(
    const __nv_bfloat16* __restrict__ QKVh,
    const __nv_bfloat16* __restrict__ QKVl,
    __nv_bfloat16* __restrict__ Oh, __nv_bfloat16* __restrict__ Ol) {
  extern __shared__ __align__(16) char sm[];
  const uint32_t smb = smem_u32(sm);

  const int tid  = threadIdx.x;
  const int lane = tid & 31;
  const int wid  = tid >> 5;

  const int b = blockIdx.x >> 8;
  const int c = blockIdx.x & 255;
  const size_t qb = ((size_t)b * 3 * NC + c) * NHW;
  const size_t kb = qb + (size_t)NC * NHW;
  const size_t vb = qb + (size_t)2 * NC * NHW;

  // Stage Q,K (group 0) and V (group 1)
  const int srow = tid >> 4, sseg = tid & 15;
#pragma unroll
  for (int r = 0; r < 8; r++) {
    int row = srow + r * 16;
    uint32_t so = (uint32_t)(row * 272 + sseg * 16);
    cp_async16(smb + AT_QH + so, QKVh + qb + row * 128 + sseg * 8);
    cp_async16(smb + AT_QL + so, QKVl + qb + row * 128 + sseg * 8);
    cp_async16(smb + AT_KH + so, QKVh + kb + row * 128 + sseg * 8);
    cp_async16(smb + AT_KL + so, QKVl + kb + row * 128 + sseg * 8);
  }
  CP_COMMIT();
#pragma unroll
  for (int r = 0; r < 8; r++) {
    int row = srow + r * 16;
    uint32_t so = (uint32_t)(row * 272 + sseg * 16);
    cp_async16(smb + AT_VH + so, QKVh + vb + row * 128 + sseg * 8);
    cp_async16(smb + AT_VL + so, QKVl + vb + row * 128 + sseg * 8);
  }
  CP_COMMIT();
  CP_WAIT1();          // Q,K ready
  __syncthreads();

  const int lr = lane & 15, lc = lane >> 4;
  const int r0 = wid * 16;

  float acc[16][4];
#pragma unroll
  for (int j = 0; j < 16; j++)
#pragma unroll
    for (int e = 0; e < 4; e++) acc[j][e] = 0.f;

  // S = Q K^T : warp covers rows r0..r0+15, all 128 cols
#pragma unroll
  for (int ks = 0; ks < 8; ks++) {
    uint32_t qh[4], ql[4];
    uint32_t ao = smb + (uint32_t)((r0 + lr) * 272 + ks * 32 + lc * 16);
    ldsm_x4(qh, ao + AT_QH);
    ldsm_x4(ql, ao + AT_QL);
#pragma unroll
    for (int nt = 0; nt < 8; nt++) {
      uint32_t kh[4], kl[4];
      uint32_t bo = smb + (uint32_t)((nt * 16 + lr) * 272 + ks * 32 + lc * 16);
      ldsm_x4(kh, bo + AT_KH);
      ldsm_x4(kl, bo + AT_KL);
      mma_bf16(acc[2 * nt],     qh, kh[0], kh[2]);
      mma_bf16(acc[2 * nt + 1], qh, kh[1], kh[3]);
      mma_bf16(acc[2 * nt],     qh, kl[0], kl[2]);
      mma_bf16(acc[2 * nt + 1], qh, kl[1], kl[3]);
      mma_bf16(acc[2 * nt],     ql, kh[0], kh[2]);
      mma_bf16(acc[2 * nt + 1], ql, kh[1], kh[3]);
    }
  }

  // Register softmax: thread owns 2 rows (g, g+8), 32 values each,
  // spread over the 4 lanes with the same lane>>2 -> shfl_xor 1,2.
  const float SCALE = 0.42044820762685725f;   // 32^(-1/4)
  float mA = -1e30f, mB = -1e30f;
#pragma unroll
  for (int j = 0; j < 16; j++) {
    acc[j][0] *= SCALE; acc[j][1] *= SCALE;
    acc[j][2] *= SCALE; acc[j][3] *= SCALE;
    mA = fmaxf(mA, fmaxf(acc[j][0], acc[j][1]));
    mB = fmaxf(mB, fmaxf(acc[j][2], acc[j][3]));
  }
  mA = fmaxf(mA, __shfl_xor_sync(0xffffffffu, mA, 1));
  mA = fmaxf(mA, __shfl_xor_sync(0xffffffffu, mA, 2));
  mB = fmaxf(mB, __shfl_xor_sync(0xffffffffu, mB, 1));
  mB = fmaxf(mB, __shfl_xor_sync(0xffffffffu, mB, 2));
  float sA = 0.f, sB = 0.f;
#pragma unroll
  for (int j = 0; j < 16; j++) {
    acc[j][0] = __expf(acc[j][0] - mA);
    acc[j][1] = __expf(acc[j][1] - mA);
    acc[j][2] = __expf(acc[j][2] - mB);
    acc[j][3] = __expf(acc[j][3] - mB);
    sA += acc[j][0] + acc[j][1];
    sB += acc[j][2] + acc[j][3];
  }
  sA += __shfl_xor_sync(0xffffffffu, sA, 1);
  sA += __shfl_xor_sync(0xffffffffu, sA, 2);
  sB += __shfl_xor_sync(0xffffffffu, sB, 1);
  sB += __shfl_xor_sync(0xffffffffu, sB, 2);
  const float rA = 1.0f / sA, rB = 1.0f / sB;

  // Convert P accumulator fragments directly to A-operand fragments (hi/lo).
  uint32_t ph[8][4], pl[8][4];
#pragma unroll
  for (int ky = 0; ky < 8; ky++) {
    const int j0 = 2 * ky, j1 = 2 * ky + 1;
    float p00 = acc[j0][0] * rA, p01 = acc[j0][1] * rA;
    float p02 = acc[j0][2] * rB, p03 = acc[j0][3] * rB;
    float p10 = acc[j1][0] * rA, p11 = acc[j1][1] * rA;
    float p12 = acc[j1][2] * rB, p13 = acc[j1][3] * rB;
    ph[ky][0] = pack_hi(p00, p01); ph[ky][1] = pack_hi(p02, p03);
    ph[ky][2] = pack_hi(p10, p11); ph[ky][3] = pack_hi(p12, p13);
    pl[ky][0] = pack_lo(p00, p01); pl[ky][1] = pack_lo(p02, p03);
    pl[ky][2] = pack_lo(p10, p11); pl[ky][3] = pack_lo(p12, p13);
  }

  CP_WAIT0();          // V ready
  __syncthreads();

  // O = P V
  float oac[16][4];
#pragma unroll
  for (int j = 0; j < 16; j++)
#pragma unroll
    for (int e = 0; e < 4; e++) oac[j][e] = 0.f;

#pragma unroll
  for (int ky = 0; ky < 8; ky++) {
#pragma unroll
    for (int nt = 0; nt < 8; nt++) {
      uint32_t vh[4], vl[4];
      uint32_t bo = smb + (uint32_t)((ky * 16 + lr) * 272 + nt * 32 + lc * 16);
      ldsm_x4_t(vh, bo + AT_VH);
      ldsm_x4_t(vl, bo + AT_VL);
      mma_bf16(oac[2 * nt],     ph[ky], vh[0], vh[1]);
      mma_bf16(oac[2 * nt + 1], ph[ky], vh[2], vh[3]);
      mma_bf16(oac[2 * nt],     ph[ky], vl[0], vl[1]);
      mma_bf16(oac[2 * nt + 1], ph[ky], vl[2], vl[3]);
      mma_bf16(oac[2 * nt],     pl[ky], vh[0], vh[1]);
      mma_bf16(oac[2 * nt + 1], pl[ky], vh[2], vh[3]);
    }
  }

  // Epilogue: write O hi/lo bf16 [b][c][row*128+col]
  const size_t ob = ((size_t)b * NC + c) * NHW;
  const int g = lane >> 2, tig = lane & 3;
  const int row0 = r0 + g, row1 = r0 + g + 8;
#pragma unroll
  for (int j = 0; j < 16; j++) {
    int col = j * 8 + tig * 2;
    size_t o0 = ob + (size_t)row0 * 128 + col;
    size_t o1 = ob + (size_t)row1 * 128 + col;
    *(uint32_t*)(Oh + o0) = pack_hi(oac[j][0], oac[j][1]);
    *(uint32_t*)(Oh + o1) = pack_hi(oac[j][2], oac[j][3]);
    *(uint32_t*)(Ol + o0) = pack_lo(oac[j][0], oac[j][1]);
    *(uint32_t*)(Ol + o1) = pack_lo(oac[j][2], oac[j][3]);
  }
}

// ---------------------------------------------------------------------------
extern "C" void kernel_launch(void* const* d_in, const int* in_sizes, int n_in,
                              void* d_out, int out_size) {
  const float* x  = (const float*)d_in[0];
  const float* wq = (const float*)d_in[1];
  const float* bq = (const float*)d_in[2];
  const float* wk = (const float*)d_in[3];
  const float* bk = (const float*)d_in[4];
  const float* wv = (const float*)d_in[5];
  const float* bv = (const float*)d_in[6];
  const float* wo = (const float*)d_in[7];
  const float* bo = (const float*)d_in[8];

  __nv_bfloat16 *xh, *xl, *qkvh, *qkvl, *ath, *atl, *wh, *wl;
  float* bias;
  cudaGetSymbolAddress((void**)&xh,   g_x_hi);
  cudaGetSymbolAddress((void**)&xl,   g_x_lo);
  cudaGetSymbolAddress((void**)&qkvh, g_qkv_hi);
  cudaGetSymbolAddress((void**)&qkvl, g_qkv_lo);
  cudaGetSymbolAddress((void**)&ath,  g_att_hi);
  cudaGetSymbolAddress((void**)&atl,  g_att_lo);
  cudaGetSymbolAddress((void**)&wh,   g_w_hi);
  cudaGetSymbolAddress((void**)&wl,   g_w_lo);
  cudaGetSymbolAddress((void**)&bias, g_bias);

  cudaFuncSetAttribute(gemm_mma,
                       cudaFuncAttributeMaxDynamicSharedMemorySize, SMEM_GEMM);
  cudaFuncSetAttribute(attn_mma,
                       cudaFuncAttributeMaxDynamicSharedMemorySize, SMEM_ATTN2);

  // Convert inputs
  split_f32<<<NB * NC * NHW / 4 / 256, 256>>>(x, xh, xl);
  convert_w<<<dim3(NC * NC / 256, 4), 256>>>(wq, wk, wv, wo, bq, bk, bv, bo, wh, wl);

  // Fused QKV projection -> bf16 hi/lo
  gemm_mma<<<dim3(NHW / 128, 6, NB), 256, SMEM_GEMM>>>(
      xh, xl, wh, wl, bias, nullptr, qkvh, qkvl, 3 * NC);

  // Tensor-core attention -> bf16 hi/lo
  attn_mma<<<NB * NC, 256, SMEM_ATTN2>>>(qkvh, qkvl, ath, atl);

  // Output projection -> fp32 d_out
  gemm_mma<<<dim3(NHW / 128, 2, NB), 256, SMEM_GEMM>>>(
      ath, atl, wh + 3 * NC * NC, wl + 3 * NC * NC, bias + 3 * NC,
      (float*)d_out, nullptr, nullptr, NC);
}